// round 1
// baseline (speedup 1.0000x reference)
#include <cuda_runtime.h>
#include <math.h>

#define N_NODES 50000
#define N_EDGES 800000
#define TOT_E   (N_EDGES + N_NODES)
#define HID     128
#define NGR     512
#define QSD     256       // 2*HID
#define NCLS    10
#define SCAN_CHUNK 1024
#define SCAN_NBLK  ((N_NODES + SCAN_CHUNK - 1) / SCAN_CHUNK)

// ---------------- scratch (device globals; no runtime allocation) ----------------
__device__ int   g_cnt[N_NODES];          // in-degree incl self loop
__device__ int   g_rowptr[N_NODES + 1];
__device__ int   g_cursor[N_NODES];
__device__ float g_dis[N_NODES];          // rsqrt(deg)
__device__ int   g_esrc[TOT_E];           // CSR (by target) source list
__device__ int   g_incl[N_NODES];         // scan temp (block-inclusive)
__device__ int   g_bsums[SCAN_NBLK];
__device__ int   g_gptr[NGR + 1];         // per-graph node ranges (batch sorted)
__device__ float g_agg[N_NODES * HID];
__device__ float g_hA[N_NODES * HID];
__device__ float g_hB[N_NODES * HID];
__device__ float g_escr[N_NODES];
__device__ float g_WT[384 * 512];         // transposed [Wih|Whh]
__device__ float g_gbias[512];            // bih+bhh
__device__ float g_gates[NGR * 512];
__device__ float g_hs[NGR * HID];
__device__ float g_cs[NGR * HID];
__device__ float g_qstar[NGR * QSD];
__device__ float g_y1[NGR * HID];
__device__ float g_y2[NGR * 64];

// ---------------- init / CSR build ----------------
__global__ void k_init() {
    int idx = blockIdx.x * blockDim.x + threadIdx.x;
    if (idx < N_NODES) g_cnt[idx] = 1;                 // self loop
    if (idx < NGR * HID) { g_hs[idx] = 0.f; g_cs[idx] = 0.f; }
    if (idx < NGR * QSD) g_qstar[idx] = 0.f;
    if (idx <= NGR) g_gptr[idx] = N_NODES;             // sentinel
}

__global__ void k_hist(const int* __restrict__ ei) {
    int e = blockIdx.x * blockDim.x + threadIdx.x;
    if (e < N_EDGES) atomicAdd(&g_cnt[ei[N_EDGES + e]], 1);
}

__global__ void k_gstart(const int* __restrict__ batch) {
    int i = blockIdx.x * blockDim.x + threadIdx.x;
    if (i < N_NODES) atomicMin(&g_gptr[batch[i]], i);
}

__global__ void k_gptr_fix() {
    // suffix min makes empty graphs collapse to empty ranges
    for (int g = NGR - 1; g >= 0; g--)
        if (g_gptr[g] > g_gptr[g + 1]) g_gptr[g] = g_gptr[g + 1];
}

__global__ void k_scan1() {
    __shared__ int s[SCAN_CHUNK];
    int tid = threadIdx.x;
    int gi = blockIdx.x * SCAN_CHUNK + tid;
    s[tid] = (gi < N_NODES) ? g_cnt[gi] : 0;
    __syncthreads();
    for (int off = 1; off < SCAN_CHUNK; off <<= 1) {
        int t = 0;
        if (tid >= off) t = s[tid - off];
        __syncthreads();
        s[tid] += t;
        __syncthreads();
    }
    if (gi < N_NODES) g_incl[gi] = s[tid];
    if (tid == SCAN_CHUNK - 1) g_bsums[blockIdx.x] = s[tid];
}

__global__ void k_scan2() {
    if (threadIdx.x == 0) {
        int run = 0;
        for (int b = 0; b < SCAN_NBLK; b++) { int t = g_bsums[b]; g_bsums[b] = run; run += t; }
    }
}

__global__ void k_scan3() {
    int i = blockIdx.x * blockDim.x + threadIdx.x;
    if (i < N_NODES) g_rowptr[i + 1] = g_incl[i] + g_bsums[i / SCAN_CHUNK];
    if (i == 0) g_rowptr[0] = 0;
}

__global__ void k_prep() {
    int i = blockIdx.x * blockDim.x + threadIdx.x;
    if (i < N_NODES) {
        g_cursor[i] = g_rowptr[i];
        g_dis[i] = rsqrtf((float)g_cnt[i]);
    }
}

__global__ void k_fill(const int* __restrict__ ei) {
    int idx = blockIdx.x * blockDim.x + threadIdx.x;
    if (idx >= TOT_E) return;
    int src, tgt;
    if (idx < N_EDGES) { src = ei[idx]; tgt = ei[N_EDGES + idx]; }
    else { src = tgt = idx - N_EDGES; }  // self loop
    int pos = atomicAdd(&g_cursor[tgt], 1);
    g_esrc[pos] = src;
}

__global__ void k_trans(const float* __restrict__ Wih, const float* __restrict__ Whh,
                        const float* __restrict__ bih, const float* __restrict__ bhh) {
    int idx = blockIdx.x * blockDim.x + threadIdx.x;
    if (idx < 384 * 512) {
        int k = idx / 512, j = idx % 512;
        g_WT[idx] = (k < 256) ? Wih[j * 256 + k] : Whh[j * 128 + (k - 256)];
    }
    if (idx < 512) g_gbias[idx] = bih[idx] + bhh[idx];
}

// ---------------- SpMM: out[i] = dis[i] * sum_{e in CSR[i]} dis[src]*in[src] ----------------
__global__ void k_spmm(const float* __restrict__ in, float* __restrict__ out) {
    int warp = threadIdx.x >> 5;
    int lane = threadIdx.x & 31;
    int i = blockIdx.x * 8 + warp;
    if (i >= N_NODES) return;
    int s = g_rowptr[i], e = g_rowptr[i + 1];
    float4 acc = make_float4(0.f, 0.f, 0.f, 0.f);
    const float4* in4 = (const float4*)in;
    #pragma unroll 4
    for (int idx = s; idx < e; idx++) {
        int src = g_esrc[idx];
        float ds = g_dis[src];
        float4 v = in4[src * 32 + lane];
        acc.x += ds * v.x; acc.y += ds * v.y; acc.z += ds * v.z; acc.w += ds * v.w;
    }
    float di = g_dis[i];
    acc.x *= di; acc.y *= di; acc.z *= di; acc.w *= di;
    ((float4*)out)[i * 32 + lane] = acc;
}

// ---------------- dense GEMM (50000x128 @ 128x128) + bias + relu ----------------
// block: 64 rows x 128 cols; 256 threads; thread: 16 rows x 2 cols
__global__ void k_gemm_relu(const float* __restrict__ A, const float* __restrict__ W,
                            const float* __restrict__ bias, float* __restrict__ C) {
    __shared__ float As[64 * 128];
    int tid = threadIdx.x;
    int r0 = blockIdx.x * 64;
    for (int idx = tid; idx < 64 * 128; idx += 256) {
        int r = idx >> 7, k = idx & 127;
        As[idx] = (r0 + r < N_NODES) ? A[(r0 + r) * 128 + k] : 0.f;
    }
    __syncthreads();
    int j0 = tid & 63;
    int rg = tid >> 6;            // 0..3, 16 rows each
    const float* Asb = &As[rg * 16 * 128];
    float acc0[16], acc1[16];
    #pragma unroll
    for (int r = 0; r < 16; r++) { acc0[r] = 0.f; acc1[r] = 0.f; }
    #pragma unroll 4
    for (int k = 0; k < 128; k++) {
        float w0 = W[k * 128 + j0];
        float w1 = W[k * 128 + j0 + 64];
        #pragma unroll
        for (int r = 0; r < 16; r++) {
            float a = Asb[r * 128 + k];
            acc0[r] += a * w0;
            acc1[r] += a * w1;
        }
    }
    float b0 = bias[j0], b1 = bias[j0 + 64];
    #pragma unroll
    for (int r = 0; r < 16; r++) {
        int rr = r0 + rg * 16 + r;
        if (rr < N_NODES) {
            C[rr * 128 + j0]      = fmaxf(acc0[r] + b0, 0.f);
            C[rr * 128 + j0 + 64] = fmaxf(acc1[r] + b1, 0.f);
        }
    }
}

// ---------------- Set2Set: LSTM gates GEMM (512x512x384) ----------------
// grid (4 jb, 32 gb), 128 threads; block: 16 graphs x 128 j
__global__ void k_gates() {
    __shared__ float As[16 * 384];
    int tid = threadIdx.x;
    int jb = blockIdx.x, gb = blockIdx.y;
    for (int idx = tid; idx < 16 * 384; idx += 128) {
        int g = idx / 384, k = idx % 384;
        int gg = gb * 16 + g;
        As[idx] = (k < 256) ? g_qstar[gg * 256 + k] : g_hs[gg * 128 + (k - 256)];
    }
    __syncthreads();
    int j = jb * 128 + tid;
    float acc[16];
    #pragma unroll
    for (int g = 0; g < 16; g++) acc[g] = 0.f;
    #pragma unroll 4
    for (int k = 0; k < 384; k++) {
        float wv = g_WT[k * 512 + j];
        #pragma unroll
        for (int g = 0; g < 16; g++) acc[g] += As[g * 384 + k] * wv;
    }
    float bb = g_gbias[j];
    #pragma unroll
    for (int g = 0; g < 16; g++) g_gates[(gb * 16 + g) * 512 + j] = acc[g] + bb;
}

__device__ __forceinline__ float sigmoidf_(float x) { return 1.f / (1.f + expf(-x)); }

__global__ void k_lstm() {
    int idx = blockIdx.x * blockDim.x + threadIdx.x;
    if (idx >= NGR * HID) return;
    int g = idx >> 7, j = idx & 127;
    const float* gr = &g_gates[g * 512];
    float ig = gr[j], fg = gr[j + 128], gg = gr[j + 256], og = gr[j + 384];
    float c = sigmoidf_(fg) * g_cs[idx] + sigmoidf_(ig) * tanhf(gg);
    g_cs[idx] = c;
    float q = sigmoidf_(og) * tanhf(c);
    g_hs[idx] = q;
    g_qstar[g * 256 + j] = q;   // q part of q_star
}

// ---------------- attention + segment softmax + weighted sum (block per graph) ----------------
__global__ void k_attn(const float* __restrict__ h) {
    __shared__ float4 sq4[32];
    __shared__ float swmax[4];
    __shared__ float semax;
    float* sq = (float*)sq4;
    int g = blockIdx.x;
    int tid = threadIdx.x;
    int lane = tid & 31, warp = tid >> 5;
    sq[tid] = g_hs[g * 128 + tid];
    __syncthreads();
    int s = g_gptr[g], e = g_gptr[g + 1];
    if (s >= e) {                        // empty graph -> r = 0
        g_qstar[g * 256 + 128 + tid] = 0.f;
        return;
    }
    // pass 1: e_i = <h_i, q>, track max (warp per node)
    float lmax = -INFINITY;
    float4 qv = sq4[lane];
    const float4* h4 = (const float4*)h;
    for (int i = s + warp; i < e; i += 4) {
        float4 hv = h4[i * 32 + lane];
        float d = hv.x * qv.x + hv.y * qv.y + hv.z * qv.z + hv.w * qv.w;
        #pragma unroll
        for (int o = 16; o > 0; o >>= 1) d += __shfl_xor_sync(0xffffffffu, d, o);
        if (lane == 0) g_escr[i] = d;
        lmax = fmaxf(lmax, d);
    }
    if (lane == 0) swmax[warp] = lmax;
    __syncthreads();
    if (tid == 0)
        semax = fmaxf(fmaxf(swmax[0], swmax[1]), fmaxf(swmax[2], swmax[3]));
    __syncthreads();
    float emax = semax;
    // pass 2: thread d accumulates r_d
    float r = 0.f, asum = 0.f;
    #pragma unroll 4
    for (int i = s; i < e; i++) {
        float w = __expf(g_escr[i] - emax);
        asum += w;
        r += w * h[i * 128 + tid];
    }
    g_qstar[g * 256 + 128 + tid] = r / (asum > 0.f ? asum : 1.f);
}

// ---------------- MLP head ----------------
__global__ void k_mlp1(const float* __restrict__ L1w, const float* __restrict__ L1b) {
    __shared__ float a[256];
    int g = blockIdx.x, j = threadIdx.x;
    a[j] = g_qstar[g * 256 + j];
    a[j + 128] = g_qstar[g * 256 + 128 + j];
    __syncthreads();
    float acc = L1b[j];
    #pragma unroll 4
    for (int k = 0; k < 256; k++) acc += a[k] * L1w[k * 128 + j];
    g_y1[g * 128 + j] = fmaxf(acc, 0.f);
}

__global__ void k_mlp2(const float* __restrict__ L2w, const float* __restrict__ L2b) {
    __shared__ float a[128];
    int g = blockIdx.x, j = threadIdx.x;
    a[j] = g_y1[g * 128 + j];
    a[j + 64] = g_y1[g * 128 + 64 + j];
    __syncthreads();
    float acc = L2b[j];
    #pragma unroll 4
    for (int k = 0; k < 128; k++) acc += a[k] * L2w[k * 64 + j];
    g_y2[g * 64 + j] = fmaxf(acc, 0.f);
}

__global__ void k_mlp3(const float* __restrict__ L3w, const float* __restrict__ L3b,
                       float* __restrict__ out) {
    __shared__ float a[64];
    __shared__ float ys[NCLS];
    int g = blockIdx.x, j = threadIdx.x;   // 32 threads
    a[j] = g_y2[g * 64 + j];
    a[j + 32] = g_y2[g * 64 + 32 + j];
    __syncthreads();
    if (j < NCLS) {
        float acc = L3b[j];
        #pragma unroll
        for (int k = 0; k < 64; k++) acc += a[k] * L3w[k * NCLS + j];
        ys[j] = acc;
    }
    __syncthreads();
    if (j < NCLS) {
        float m = ys[0];
        #pragma unroll
        for (int k = 1; k < NCLS; k++) m = fmaxf(m, ys[k]);
        float se = 0.f;
        #pragma unroll
        for (int k = 0; k < NCLS; k++) se += expf(ys[k] - m);
        out[g * NCLS + j] = ys[j] - m - logf(se);
    }
}

// ---------------- launcher ----------------
extern "C" void kernel_launch(void* const* d_in, const int* in_sizes, int n_in,
                              void* d_out, int out_size) {
    const float* x     = (const float*)d_in[0];
    const int*   ei    = (const int*)  d_in[1];
    const int*   batch = (const int*)  d_in[2];
    const float* W1 = (const float*)d_in[3];  const float* b1 = (const float*)d_in[4];
    const float* W2 = (const float*)d_in[5];  const float* b2 = (const float*)d_in[6];
    const float* W3 = (const float*)d_in[7];  const float* b3 = (const float*)d_in[8];
    const float* Wih = (const float*)d_in[9]; const float* Whh = (const float*)d_in[10];
    const float* bih = (const float*)d_in[11];const float* bhh = (const float*)d_in[12];
    const float* L1w = (const float*)d_in[13];const float* L1b = (const float*)d_in[14];
    const float* L2w = (const float*)d_in[15];const float* L2b = (const float*)d_in[16];
    const float* L3w = (const float*)d_in[17];const float* L3b = (const float*)d_in[18];
    float* out = (float*)d_out;

    // init + CSR build
    k_init<<<(NGR * QSD + 255) / 256, 256>>>();
    k_hist<<<(N_EDGES + 255) / 256, 256>>>(ei);
    k_gstart<<<(N_NODES + 255) / 256, 256>>>(batch);
    k_scan1<<<SCAN_NBLK, SCAN_CHUNK>>>();
    k_scan2<<<1, 32>>>();
    k_scan3<<<(N_NODES + 255) / 256, 256>>>();
    k_gptr_fix<<<1, 1>>>();
    k_prep<<<(N_NODES + 255) / 256, 256>>>();
    k_fill<<<(TOT_E + 255) / 256, 256>>>(ei);
    k_trans<<<(384 * 512 + 255) / 256, 256>>>(Wih, Whh, bih, bhh);

    int spmm_grid = (N_NODES + 7) / 8;
    int gemm_grid = (N_NODES + 63) / 64;

    // 3 GCN layers (aggregate first, then transform: valid by linearity)
    k_spmm<<<spmm_grid, 256>>>(x, g_agg);
    k_gemm_relu<<<gemm_grid, 256>>>(g_agg, W1, b1, g_hA);
    k_spmm<<<spmm_grid, 256>>>(g_hA, g_agg);
    k_gemm_relu<<<gemm_grid, 256>>>(g_agg, W2, b2, g_hB);
    k_spmm<<<spmm_grid, 256>>>(g_hB, g_agg);
    k_gemm_relu<<<gemm_grid, 256>>>(g_agg, W3, b3, g_hA);

    // Set2Set (4 processing steps); final node embedding = g_hA
    for (int step = 0; step < 4; step++) {
        k_gates<<<dim3(4, 32), 128>>>();
        k_lstm<<<(NGR * HID + 255) / 256, 256>>>();
        k_attn<<<NGR, 128>>>(g_hA);
    }

    // MLP head + log_softmax
    k_mlp1<<<NGR, 128>>>(L1w, L1b);
    k_mlp2<<<NGR, 64>>>(L2w, L2b);
    k_mlp3<<<NGR, 32>>>(L3w, L3b, out);
}